// round 14
// baseline (speedup 1.0000x reference)
#include <cuda_runtime.h>
#include <cuda_bf16.h>
#include <cstdint>
#include <cstddef>

// ---------------------------------------------------------------------------
// MambaBlock: b=2, L=1024, d_model=1024, d_inner=2048, d_state=16, d_conv=4
// bf16x3 mma.sync GEMMs everywhere + conv/gate + chunked selective scan
// ---------------------------------------------------------------------------

namespace {
constexpr int kDI   = 2048;
constexpr int kDS   = 16;
constexpr int kL    = 1024;
constexpr int kB    = 2;
constexpr int kDM   = 1024;
constexpr int kRows = kB * kL;        // 2048
constexpr int kNP   = 2 * kDS + 1;    // 33
constexpr int kNPP  = 128;            // padded proj N
constexpr int kNCH  = 64;             // scan chunks
constexpr int kTCH  = kL / kNCH;      // 16
constexpr int kPKS  = 8;              // proj K splits

constexpr int MATB   = 128 * 64;              // 8192 (128 rows x 64B)
constexpr int STAGEB = 4 * MATB;              // 32768
constexpr int STAGES = 3;
constexpr int TC_SMEM = STAGES * STAGEB;      // 98304 -> 2 CTAs/SM
}

// Scratch (allocation-free rule: device globals)
__device__ float g_xz[(size_t)kRows * 2 * kDI];
__device__ float g_xh[(size_t)kRows * kDI];
__device__ float g_proj[(size_t)kRows * kNP];
__device__ float g_projp[(size_t)kPKS * kRows * kNPP];
__device__ float g_part[(size_t)kRows * kDM];
__device__ float g_aprod [(size_t)kB * kNCH * kDI * kDS];
__device__ float g_hloc  [(size_t)kB * kNCH * kDI * kDS];
__device__ float g_hstart[(size_t)kB * kNCH * kDI * kDS];
__device__ unsigned short g_xhi [(size_t)kRows * kDM];
__device__ unsigned short g_xlo [(size_t)kRows * kDM];
__device__ unsigned short g_wihi[(size_t)2 * kDI * kDM];
__device__ unsigned short g_wilo[(size_t)2 * kDI * kDM];
__device__ unsigned short g_wohi[(size_t)kDM * kDI];
__device__ unsigned short g_wolo[(size_t)kDM * kDI];
__device__ unsigned short g_wphi[(size_t)kNPP * kDI];
__device__ unsigned short g_wplo[(size_t)kNPP * kDI];
__device__ unsigned short g_xhhi[(size_t)kRows * kDI];
__device__ unsigned short g_xhlo[(size_t)kRows * kDI];
__device__ unsigned short g_yhi [(size_t)kRows * kDI];
__device__ unsigned short g_ylo [(size_t)kRows * kDI];

// ---------------------------------------------------------------------------
// PTX helpers
// ---------------------------------------------------------------------------
__device__ __forceinline__ uint32_t smem_u32(const void* p) {
    uint32_t a;
    asm("{ .reg .u64 t; cvta.to.shared.u64 t, %1; cvt.u32.u64 %0, t; }" : "=r"(a) : "l"(p));
    return a;
}
__device__ __forceinline__ void cp16(uint32_t saddr, const void* gaddr) {
    asm volatile("cp.async.cg.shared.global [%0], [%1], 16;" :: "r"(saddr), "l"(gaddr));
}
__device__ __forceinline__ void ldsm_x4(uint32_t a, uint32_t r[4]) {
    asm volatile("ldmatrix.sync.aligned.m8n8.x4.shared.b16 {%0,%1,%2,%3}, [%4];"
                 : "=r"(r[0]), "=r"(r[1]), "=r"(r[2]), "=r"(r[3]) : "r"(a));
}
__device__ __forceinline__ void mma_bf16(float c[4], const uint32_t a[4], const uint32_t b[2]) {
    asm volatile(
        "mma.sync.aligned.m16n8k16.row.col.f32.bf16.bf16.f32 "
        "{%0,%1,%2,%3}, {%4,%5,%6,%7}, {%8,%9}, {%0,%1,%2,%3};"
        : "+f"(c[0]), "+f"(c[1]), "+f"(c[2]), "+f"(c[3])
        : "r"(a[0]), "r"(a[1]), "r"(a[2]), "r"(a[3]), "r"(b[0]), "r"(b[1]));
}
__device__ __forceinline__ uint32_t swz(uint32_t r, uint32_t c) {
    return r * 64u + ((c ^ ((r >> 1) & 3u)) << 4);
}
__device__ __forceinline__ void split_bf16(float x, unsigned short& hi, unsigned short& lo) {
    const __nv_bfloat16 h = __float2bfloat16(x);
    hi = __bfloat16_as_ushort(h);
    lo = __bfloat16_as_ushort(__float2bfloat16(x - __bfloat162float(h)));
}

// ---------------------------------------------------------------------------
// float -> (bf16 hi, bf16 lo) splits: x, in_w, out_w, padded xproj_w (1 launch)
// ---------------------------------------------------------------------------
__global__ void __launch_bounds__(256)
cvt4_kernel(const float* __restrict__ a, unsigned short* __restrict__ ahi,
            unsigned short* __restrict__ alo, int na,
            const float* __restrict__ b, unsigned short* __restrict__ bhi,
            unsigned short* __restrict__ blo, int nb,
            const float* __restrict__ c, unsigned short* __restrict__ chi,
            unsigned short* __restrict__ clo, int nc,
            const float* __restrict__ wp)
{
    int i = blockIdx.x * 256 + threadIdx.x;
    if (i < na) { split_bf16(a[i], ahi[i], alo[i]); return; }
    i -= na;
    if (i < nb) { split_bf16(b[i], bhi[i], blo[i]); return; }
    i -= nb;
    if (i < nc) { split_bf16(c[i], chi[i], clo[i]); return; }
    i -= nc;
    if (i >= kNPP * kDI) return;
    const int n = i >> 11;
    const float v = (n < kNP) ? wp[i] : 0.0f;
    split_bf16(v, g_wphi[i], g_wplo[i]);
}

// ---------------------------------------------------------------------------
// bf16x3 NT GEMM: C[m,n] = sum_{k in [z*KL,(z+1)*KL)} A[m,k]*B[n,k] (+bias[n])
// z=0 writes C; z>=1 writes Cpart + (z-1)*zstride.
// Register-double-buffered B fragments; cp.async issued after kh0 B loads.
// ---------------------------------------------------------------------------
template <bool BIAS>
__global__ void __launch_bounds__(256, 2)
gemm_bf16x3_kernel(const unsigned short* __restrict__ Ahi,
                   const unsigned short* __restrict__ Alo,
                   const unsigned short* __restrict__ Bhi,
                   const unsigned short* __restrict__ Blo,
                   const float* __restrict__ bias, float* __restrict__ C,
                   float* __restrict__ Cpart, size_t zstride, int K, int KL, int N)
{
    extern __shared__ char sm[];
    const uint32_t sbase = smem_u32(sm);
    const int tid  = threadIdx.x;
    const int wid  = tid >> 5;
    const int lane = tid & 31;
    const int m0 = blockIdx.y * 128;
    const int n0 = blockIdx.x * 128;
    const int koff = blockIdx.z * KL;
    const int wm = wid & 1;
    const int wn = wid >> 1;

    const unsigned short* mats[4] = {
        Ahi + (size_t)m0 * K + koff, Alo + (size_t)m0 * K + koff,
        Bhi + (size_t)n0 * K + koff, Blo + (size_t)n0 * K + koff };

    const int NK = KL >> 5;

    const int lm = tid >> 6;
    const int lt = tid & 63;
    const unsigned short* gmat = mats[lm];

    auto issue_stage = [&](int kc) {
        const uint32_t sb = sbase + (uint32_t)(kc % STAGES) * STAGEB + lm * MATB;
        const char* gb = (const char*)(gmat) + (size_t)kc * 64;
#pragma unroll
        for (int j = 0; j < 8; j++) {
            const int id  = lt + j * 64;
            const uint32_t row = id >> 2;
            const uint32_t c16 = id & 3;
            cp16(sb + swz(row, c16), gb + (size_t)row * K * 2 + c16 * 16);
        }
    };

    issue_stage(0);
    asm volatile("cp.async.commit_group;");
    issue_stage(1);
    asm volatile("cp.async.commit_group;");

    float acc[4][4][4];
#pragma unroll
    for (int mt = 0; mt < 4; mt++)
#pragma unroll
        for (int nt = 0; nt < 4; nt++)
#pragma unroll
            for (int r = 0; r < 4; r++) acc[mt][nt][r] = 0.0f;

    const int ag = lane >> 3;
    const uint32_t arow = (ag & 1) * 8 + (lane & 7);
    const uint32_t ac0  = (uint32_t)(ag >> 1);
    // B x4 addressing (validated R12)
    const uint32_t brow4 = ((lane >> 4) & 1) * 8 + (lane & 7);
    const uint32_t bc0   = (uint32_t)((lane >> 3) & 1);

    for (int kc = 0; kc < NK; kc++) {
        asm volatile("cp.async.wait_group 1;");
        __syncthreads();

        const uint32_t stg = sbase + (uint32_t)(kc % STAGES) * STAGEB;
        const uint32_t bAhi = stg + 0 * MATB;
        const uint32_t bAlo = stg + 1 * MATB;
        const uint32_t bBhi = stg + 2 * MATB;
        const uint32_t bBlo = stg + 3 * MATB;

        uint32_t fBh[2][4][2], fBl[2][4][2];
        auto load_B = [&](int kh) {
            const uint32_t cb = bc0 + kh * 2;
#pragma unroll
            for (int ntp = 0; ntp < 2; ntp++) {
                const uint32_t rB = wn * 32 + ntp * 16 + brow4;
                const uint32_t o = swz(rB, cb);
                ldsm_x4(bBhi + o, fBh[kh][ntp * 2]);
                ldsm_x4(bBlo + o, fBl[kh][ntp * 2]);
            }
        };

        load_B(0);          // fragments for kh=0, needed first
        load_B(1);          // prefetch kh=1 fragments
        if (kc + 2 < NK) issue_stage(kc + 2);   // then queue next-stage cp.asyncs
        asm volatile("cp.async.commit_group;");

#pragma unroll
        for (int kh = 0; kh < 2; kh++) {
            const uint32_t ca = ac0 + kh * 2;
#pragma unroll
            for (int mt = 0; mt < 4; mt++) {
                const uint32_t rA = wm * 64 + mt * 16 + arow;
                const uint32_t o = swz(rA, ca);
                uint32_t fAh[4], fAl[4];
                ldsm_x4(bAhi + o, fAh);
                ldsm_x4(bAlo + o, fAl);
#pragma unroll
                for (int nt = 0; nt < 4; nt++) {
                    mma_bf16(acc[mt][nt], fAh, fBh[kh][nt]);
                    mma_bf16(acc[mt][nt], fAh, fBl[kh][nt]);
                    mma_bf16(acc[mt][nt], fAl, fBh[kh][nt]);
                }
            }
        }
    }

    float* Cout = (blockIdx.z == 0) ? C : (Cpart + (size_t)(blockIdx.z - 1) * zstride);
    const int gid = lane >> 2;
    const int tig = lane & 3;
#pragma unroll
    for (int mt = 0; mt < 4; mt++) {
        const int r0 = m0 + wm * 64 + mt * 16 + gid;
#pragma unroll
        for (int nt = 0; nt < 4; nt++) {
            const int c = n0 + wn * 32 + nt * 8 + 2 * tig;
            float b0 = 0.0f, b1 = 0.0f;
            if (BIAS) { b0 = bias[c]; b1 = bias[c + 1]; }
            float2 v0 = make_float2(acc[mt][nt][0] + b0, acc[mt][nt][1] + b1);
            float2 v1 = make_float2(acc[mt][nt][2] + b0, acc[mt][nt][3] + b1);
            *(float2*)(&Cout[(size_t)r0 * N + c])       = v0;
            *(float2*)(&Cout[(size_t)(r0 + 8) * N + c]) = v1;
        }
    }
}

// out += part (float4)
__global__ void __launch_bounds__(256)
add_kernel(float* __restrict__ out, const float* __restrict__ part, int n4)
{
    const int i = blockIdx.x * 256 + threadIdx.x;
    if (i < n4) {
        float4 o = ((const float4*)out)[i];
        const float4 p = ((const float4*)part)[i];
        o.x += p.x; o.y += p.y; o.z += p.z; o.w += p.w;
        ((float4*)out)[i] = o;
    }
}

// combine kPKS proj partials (N=128 padded) -> g_proj (N=33)
__global__ void __launch_bounds__(256)
proj_combine_kernel()
{
    const int i = blockIdx.x * 256 + threadIdx.x;
    if (i >= kRows * kNP) return;
    const int row = i / kNP;
    const int n = i - row * kNP;
    float s = 0.0f;
#pragma unroll
    for (int z = 0; z < kPKS; z++)
        s += g_projp[((size_t)z * kRows + row) * kNPP + n];
    g_proj[i] = s;
}

// ---------------------------------------------------------------------------
// Depthwise causal conv (D_CONV=4) + bias + SiLU(z) gate.
// Also emits xh as bf16 hi/lo for the proj GEMM.
// ---------------------------------------------------------------------------
__global__ void __launch_bounds__(256)
conv_gate_kernel(const float* __restrict__ conv_w,
                 const float* __restrict__ conv_b)
{
    const int idx = blockIdx.x * 256 + threadIdx.x;
    const int i = idx & (kDI - 1);
    const int t = (idx >> 11) & (kL - 1);
    const int b = idx >> 21;

    const float* base = g_xz + (size_t)b * kL * (2 * kDI) + i;
    float accv = conv_b[i];
#pragma unroll
    for (int k = 0; k < 4; k++) {
        const int tt = t + k - 3;
        if (tt >= 0) accv += conv_w[i * 4 + k] * base[(size_t)tt * (2 * kDI)];
    }
    const float z = g_xz[((size_t)(b * kL + t)) * (2 * kDI) + kDI + i];
    const float sig = 1.0f / (1.0f + __expf(-z));
    const float xh = accv * (z * sig);
    g_xh[idx] = xh;
    split_bf16(xh, g_xhhi[idx], g_xhlo[idx]);
}

// ---------------------------------------------------------------------------
// Chunked selective scan. delta = exp(softplus(.)) = 1 + exp(.) identity.
// ---------------------------------------------------------------------------
__global__ void __launch_bounds__(256)
scan_pass1_kernel(const float* __restrict__ dt_w,
                  const float* __restrict__ dt_b,
                  const float* __restrict__ A_log)
{
    const int gi = blockIdx.x;
    const int b = gi / (kNCH * (kDI / 256));
    const int c = (gi / (kDI / 256)) % kNCH;
    const int i = (gi % (kDI / 256)) * 256 + threadIdx.x;

    constexpr float kLog2e = 1.4426950408889634f;
    float Arow[kDS], h[kDS], P[kDS];
#pragma unroll
    for (int s = 0; s < kDS; s++) {
        Arow[s] = -__expf(A_log[i * kDS + s]) * kLog2e;
        h[s] = 0.0f;
        P[s] = 1.0f;
    }
    const float dtw = dt_w[i];
    const float dtb = dt_b[i];

    __shared__ float sp[kTCH * kNP];
    {
        const size_t base = (size_t)(b * kL + c * kTCH) * kNP;
        for (int idx = threadIdx.x; idx < kTCH * kNP; idx += 256)
            sp[idx] = g_proj[base + idx];
    }
    __syncthreads();

    for (int tt = 0; tt < kTCH; tt++) {
        const int t = c * kTCH + tt;
        const float* row = sp + tt * kNP;
        const float xt = g_xh[((size_t)(b * kL + t)) * kDI + i];
        const float delta = 1.0f + __expf(row[0] * dtw + dtb);
        const float dx = delta * xt;
#pragma unroll
        for (int s = 0; s < kDS; s++) {
            const float a = exp2f(Arow[s] * delta);
            h[s] = a * h[s] + row[1 + s] * dx;
            P[s] *= a;
        }
    }

    const size_t o = (((size_t)(b * kNCH + c)) * kDI + i) * kDS;
#pragma unroll
    for (int v = 0; v < kDS / 4; v++) {
        *(float4*)(g_aprod + o + v * 4) = make_float4(P[v*4], P[v*4+1], P[v*4+2], P[v*4+3]);
        *(float4*)(g_hloc  + o + v * 4) = make_float4(h[v*4], h[v*4+1], h[v*4+2], h[v*4+3]);
    }
}

__global__ void __launch_bounds__(256)
scan_combine_kernel()
{
    const int idx = blockIdx.x * 256 + threadIdx.x;
    const int b = idx >> 15;
    const int rem = idx & ((kDI * kDS) - 1);
    float h = 0.0f;
#pragma unroll 4
    for (int c = 0; c < kNCH; c++) {
        const size_t o = ((size_t)(b * kNCH + c)) * (kDI * kDS) + rem;
        g_hstart[o] = h;
        h = g_aprod[o] * h + g_hloc[o];
    }
}

__global__ void __launch_bounds__(256)
scan_pass3_kernel(const float* __restrict__ dt_w,
                  const float* __restrict__ dt_b,
                  const float* __restrict__ A_log,
                  const float* __restrict__ Dv)
{
    const int gi = blockIdx.x;
    const int b = gi / (kNCH * (kDI / 256));
    const int c = (gi / (kDI / 256)) % kNCH;
    const int i = (gi % (kDI / 256)) * 256 + threadIdx.x;

    constexpr float kLog2e = 1.4426950408889634f;
    float Arow[kDS], h[kDS];
    {
        const size_t o = (((size_t)(b * kNCH + c)) * kDI + i) * kDS;
#pragma unroll
        for (int v = 0; v < kDS / 4; v++) {
            float4 hv = *(const float4*)(g_hstart + o + v * 4);
            h[v*4] = hv.x; h[v*4+1] = hv.y; h[v*4+2] = hv.z; h[v*4+3] = hv.w;
        }
    }
#pragma unroll
    for (int s = 0; s < kDS; s++)
        Arow[s] = -__expf(A_log[i * kDS + s]) * kLog2e;

    const float dtw = dt_w[i];
    const float dtb = dt_b[i];
    const float Di  = Dv[i];

    __shared__ float sp[kTCH * kNP];
    {
        const size_t base = (size_t)(b * kL + c * kTCH) * kNP;
        for (int idx = threadIdx.x; idx < kTCH * kNP; idx += 256)
            sp[idx] = g_proj[base + idx];
    }
    __syncthreads();

    for (int tt = 0; tt < kTCH; tt++) {
        const int t = c * kTCH + tt;
        const float* row = sp + tt * kNP;
        const size_t oy = ((size_t)(b * kL + t)) * kDI + i;
        const float xt = g_xh[oy];
        const float delta = 1.0f + __expf(row[0] * dtw + dtb);
        const float dx = delta * xt;
        float yv = 0.0f;
#pragma unroll
        for (int s = 0; s < kDS; s++) {
            const float a = exp2f(Arow[s] * delta);
            h[s] = a * h[s] + row[1 + s] * dx;
            yv += h[s] * row[1 + kDS + s];
        }
        const float yf = yv + Di * xt;
        split_bf16(yf, g_yhi[oy], g_ylo[oy]);
    }
}

// ---------------------------------------------------------------------------
// Launch
// ---------------------------------------------------------------------------
extern "C" void kernel_launch(void* const* d_in, const int* in_sizes, int n_in,
                              void* d_out, int out_size)
{
    const float* x       = (const float*)d_in[0];
    const float* in_w    = (const float*)d_in[1];
    const float* in_b    = (const float*)d_in[2];
    const float* conv_w  = (const float*)d_in[3];
    const float* conv_b  = (const float*)d_in[4];
    const float* xproj_w = (const float*)d_in[5];
    const float* dt_w    = (const float*)d_in[6];
    const float* dt_b    = (const float*)d_in[7];
    const float* A_log   = (const float*)d_in[8];
    const float* Dv      = (const float*)d_in[9];
    const float* out_w   = (const float*)d_in[10];
    float* out = (float*)d_out;

    float *xz_p, *part_p, *projp_p;
    unsigned short *xhi, *xlo, *wihi, *wilo, *wohi, *wolo, *yhi, *ylo;
    unsigned short *xhhi, *xhlo;
    cudaGetSymbolAddress((void**)&xz_p,    g_xz);
    cudaGetSymbolAddress((void**)&part_p,  g_part);
    cudaGetSymbolAddress((void**)&projp_p, g_projp);
    cudaGetSymbolAddress((void**)&xhi,  g_xhi);
    cudaGetSymbolAddress((void**)&xlo,  g_xlo);
    cudaGetSymbolAddress((void**)&wihi, g_wihi);
    cudaGetSymbolAddress((void**)&wilo, g_wilo);
    cudaGetSymbolAddress((void**)&wohi, g_wohi);
    cudaGetSymbolAddress((void**)&wolo, g_wolo);
    cudaGetSymbolAddress((void**)&xhhi, g_xhhi);
    cudaGetSymbolAddress((void**)&xhlo, g_xhlo);
    cudaGetSymbolAddress((void**)&yhi,  g_yhi);
    cudaGetSymbolAddress((void**)&ylo,  g_ylo);

    unsigned short *wphi, *wplo;
    cudaGetSymbolAddress((void**)&wphi, g_wphi);
    cudaGetSymbolAddress((void**)&wplo, g_wplo);

    cudaFuncSetAttribute(gemm_bf16x3_kernel<true>,
                         cudaFuncAttributeMaxDynamicSharedMemorySize, TC_SMEM);
    cudaFuncSetAttribute(gemm_bf16x3_kernel<false>,
                         cudaFuncAttributeMaxDynamicSharedMemorySize, TC_SMEM);

    // hi/lo splits (x, in_w, out_w, padded xproj_w) in one launch
    {
        const int n1 = kRows * kDM;
        const int n2 = 2 * kDI * kDM;
        const int n3 = kDM * kDI;
        const int tot = n1 + n2 + n3 + kNPP * kDI;
        cvt4_kernel<<<(tot + 255) / 256, 256>>>(x, xhi, xlo, n1,
                                                in_w, wihi, wilo, n2,
                                                out_w, wohi, wolo, n3,
                                                xproj_w);
    }

    // GEMM1: xz = x @ in_w^T + in_b   (M=2048, N=4096, K=1024)
    {
        dim3 grid((2 * kDI) / 128, kRows / 128, 1);
        gemm_bf16x3_kernel<true><<<grid, 256, TC_SMEM>>>(
            xhi, xlo, wihi, wilo, in_b, xz_p, nullptr, 0, kDM, kDM, 2 * kDI);
    }
    // conv + SiLU gate (also emits xh hi/lo)
    conv_gate_kernel<<<(kRows * kDI) / 256, 256>>>(conv_w, conv_b);
    // xproj via MMA GEMM: proj_padded = xh @ wpad^T, split-K=8, then combine
    {
        dim3 grid(1, kRows / 128, kPKS);
        gemm_bf16x3_kernel<false><<<grid, 256, TC_SMEM>>>(
            xhhi, xhlo, wphi, wplo, nullptr,
            projp_p, projp_p + (size_t)kRows * kNPP, (size_t)kRows * kNPP,
            kDI, kDI / kPKS, kNPP);
        proj_combine_kernel<<<(kRows * kNP + 255) / 256, 256>>>();
    }
    // chunked selective scan (pass3 emits y as bf16 hi/lo)
    {
        const int grid_scan = kB * kNCH * (kDI / 256);   // 1024
        scan_pass1_kernel<<<grid_scan, 256>>>(dt_w, dt_b, A_log);
        scan_combine_kernel<<<(kB * kDI * kDS) / 256, 256>>>();
        scan_pass3_kernel<<<grid_scan, 256>>>(dt_w, dt_b, A_log, Dv);
    }
    // GEMM2: out = y @ out_w^T  (M=2048, N=1024, K=2048), split-K=2
    {
        dim3 grid(kDM / 128, kRows / 128, 2);
        gemm_bf16x3_kernel<false><<<grid, 256, TC_SMEM>>>(
            yhi, ylo, wohi, wolo, nullptr, out, part_p, 0, kDI, kDI / 2, kDM);
        add_kernel<<<(kRows * kDM / 4 + 255) / 256, 256>>>(out, part_p, kRows * kDM / 4);
    }
}

// round 15
// speedup vs baseline: 1.0219x; 1.0219x over previous
#include <cuda_runtime.h>
#include <cuda_bf16.h>
#include <cstdint>
#include <cstddef>

// ---------------------------------------------------------------------------
// MambaBlock: b=2, L=1024, d_model=1024, d_inner=2048, d_state=16, d_conv=4
// bf16x3 mma.sync GEMMs everywhere + conv/gate + chunked selective scan
// ---------------------------------------------------------------------------

namespace {
constexpr int kDI   = 2048;
constexpr int kDS   = 16;
constexpr int kL    = 1024;
constexpr int kB    = 2;
constexpr int kDM   = 1024;
constexpr int kRows = kB * kL;        // 2048
constexpr int kNP   = 2 * kDS + 1;    // 33
constexpr int kNPP  = 128;            // padded proj N
constexpr int kNCH  = 64;             // scan chunks
constexpr int kTCH  = kL / kNCH;      // 16
constexpr int kPKS  = 8;              // proj K splits

constexpr int MATB   = 128 * 64;              // 8192 (128 rows x 64B)
constexpr int STAGEB = 4 * MATB;              // 32768
constexpr int STAGES = 3;
constexpr int TC_SMEM = STAGES * STAGEB;      // 98304 -> 2 CTAs/SM
}

// Scratch (allocation-free rule: device globals)
__device__ float g_xz[(size_t)kRows * 2 * kDI];
__device__ float g_xh[(size_t)kRows * kDI];
__device__ float g_projp[(size_t)kPKS * kRows * kNPP];
__device__ float g_part[(size_t)kRows * kDM];
__device__ float g_aprod [(size_t)kB * kNCH * kDI * kDS];
__device__ float g_hloc  [(size_t)kB * kNCH * kDI * kDS];
__device__ float g_hstart[(size_t)kB * kNCH * kDI * kDS];
__device__ unsigned short g_xhi [(size_t)kRows * kDM];
__device__ unsigned short g_xlo [(size_t)kRows * kDM];
__device__ unsigned short g_wihi[(size_t)2 * kDI * kDM];
__device__ unsigned short g_wilo[(size_t)2 * kDI * kDM];
__device__ unsigned short g_wohi[(size_t)kDM * kDI];
__device__ unsigned short g_wolo[(size_t)kDM * kDI];
__device__ unsigned short g_wphi[(size_t)kNPP * kDI];
__device__ unsigned short g_wplo[(size_t)kNPP * kDI];
__device__ unsigned short g_xhhi[(size_t)kRows * kDI];
__device__ unsigned short g_xhlo[(size_t)kRows * kDI];
__device__ unsigned short g_yhi [(size_t)kRows * kDI];
__device__ unsigned short g_ylo [(size_t)kRows * kDI];

// ---------------------------------------------------------------------------
// PTX helpers
// ---------------------------------------------------------------------------
__device__ __forceinline__ uint32_t smem_u32(const void* p) {
    uint32_t a;
    asm("{ .reg .u64 t; cvta.to.shared.u64 t, %1; cvt.u32.u64 %0, t; }" : "=r"(a) : "l"(p));
    return a;
}
__device__ __forceinline__ void cp16(uint32_t saddr, const void* gaddr) {
    asm volatile("cp.async.cg.shared.global [%0], [%1], 16;" :: "r"(saddr), "l"(gaddr));
}
__device__ __forceinline__ void ldsm_x4(uint32_t a, uint32_t r[4]) {
    asm volatile("ldmatrix.sync.aligned.m8n8.x4.shared.b16 {%0,%1,%2,%3}, [%4];"
                 : "=r"(r[0]), "=r"(r[1]), "=r"(r[2]), "=r"(r[3]) : "r"(a));
}
__device__ __forceinline__ void mma_bf16(float c[4], const uint32_t a[4], const uint32_t b[2]) {
    asm volatile(
        "mma.sync.aligned.m16n8k16.row.col.f32.bf16.bf16.f32 "
        "{%0,%1,%2,%3}, {%4,%5,%6,%7}, {%8,%9}, {%0,%1,%2,%3};"
        : "+f"(c[0]), "+f"(c[1]), "+f"(c[2]), "+f"(c[3])
        : "r"(a[0]), "r"(a[1]), "r"(a[2]), "r"(a[3]), "r"(b[0]), "r"(b[1]));
}
__device__ __forceinline__ uint32_t swz(uint32_t r, uint32_t c) {
    return r * 64u + ((c ^ ((r >> 1) & 3u)) << 4);
}
__device__ __forceinline__ void split_bf16(float x, unsigned short& hi, unsigned short& lo) {
    const __nv_bfloat16 h = __float2bfloat16(x);
    hi = __bfloat16_as_ushort(h);
    lo = __bfloat16_as_ushort(__float2bfloat16(x - __bfloat162float(h)));
}

// ---------------------------------------------------------------------------
// float -> (bf16 hi, bf16 lo) splits: x, in_w, out_w, padded xproj_w (1 launch)
// ---------------------------------------------------------------------------
__global__ void __launch_bounds__(256)
cvt4_kernel(const float* __restrict__ a, unsigned short* __restrict__ ahi,
            unsigned short* __restrict__ alo, int na,
            const float* __restrict__ b, unsigned short* __restrict__ bhi,
            unsigned short* __restrict__ blo, int nb,
            const float* __restrict__ c, unsigned short* __restrict__ chi,
            unsigned short* __restrict__ clo, int nc,
            const float* __restrict__ wp)
{
    int i = blockIdx.x * 256 + threadIdx.x;
    if (i < na) { split_bf16(a[i], ahi[i], alo[i]); return; }
    i -= na;
    if (i < nb) { split_bf16(b[i], bhi[i], blo[i]); return; }
    i -= nb;
    if (i < nc) { split_bf16(c[i], chi[i], clo[i]); return; }
    i -= nc;
    if (i >= kNPP * kDI) return;
    const int n = i >> 11;
    const float v = (n < kNP) ? wp[i] : 0.0f;
    split_bf16(v, g_wphi[i], g_wplo[i]);
}

// ---------------------------------------------------------------------------
// bf16x3 NT GEMM (R12-proven mainloop): C[m,n] = sum A[m,k]*B[n,k] (+bias)
// z=0 writes C; z>=1 writes Cpart + (z-1)*zstride.
// ---------------------------------------------------------------------------
template <bool BIAS>
__global__ void __launch_bounds__(256, 2)
gemm_bf16x3_kernel(const unsigned short* __restrict__ Ahi,
                   const unsigned short* __restrict__ Alo,
                   const unsigned short* __restrict__ Bhi,
                   const unsigned short* __restrict__ Blo,
                   const float* __restrict__ bias, float* __restrict__ C,
                   float* __restrict__ Cpart, size_t zstride, int K, int KL, int N)
{
    extern __shared__ char sm[];
    const uint32_t sbase = smem_u32(sm);
    const int tid  = threadIdx.x;
    const int wid  = tid >> 5;
    const int lane = tid & 31;
    const int m0 = blockIdx.y * 128;
    const int n0 = blockIdx.x * 128;
    const int koff = blockIdx.z * KL;
    const int wm = wid & 1;
    const int wn = wid >> 1;

    const unsigned short* mats[4] = {
        Ahi + (size_t)m0 * K + koff, Alo + (size_t)m0 * K + koff,
        Bhi + (size_t)n0 * K + koff, Blo + (size_t)n0 * K + koff };

    const int NK = KL >> 5;

    const int lm = tid >> 6;
    const int lt = tid & 63;
    const unsigned short* gmat = mats[lm];

    auto issue_stage = [&](int kc) {
        const uint32_t sb = sbase + (uint32_t)(kc % STAGES) * STAGEB + lm * MATB;
        const char* gb = (const char*)(gmat) + (size_t)kc * 64;
#pragma unroll
        for (int j = 0; j < 8; j++) {
            const int id  = lt + j * 64;
            const uint32_t row = id >> 2;
            const uint32_t c16 = id & 3;
            cp16(sb + swz(row, c16), gb + (size_t)row * K * 2 + c16 * 16);
        }
    };

    issue_stage(0);
    asm volatile("cp.async.commit_group;");
    issue_stage(1);
    asm volatile("cp.async.commit_group;");

    float acc[4][4][4];
#pragma unroll
    for (int mt = 0; mt < 4; mt++)
#pragma unroll
        for (int nt = 0; nt < 4; nt++)
#pragma unroll
            for (int r = 0; r < 4; r++) acc[mt][nt][r] = 0.0f;

    const int ag = lane >> 3;
    const uint32_t arow = (ag & 1) * 8 + (lane & 7);
    const uint32_t ac0  = (uint32_t)(ag >> 1);
    // B x4 addressing (validated R12)
    const uint32_t brow4 = ((lane >> 4) & 1) * 8 + (lane & 7);
    const uint32_t bc0   = (uint32_t)((lane >> 3) & 1);

    for (int kc = 0; kc < NK; kc++) {
        asm volatile("cp.async.wait_group 1;");
        __syncthreads();
        if (kc + 2 < NK) issue_stage(kc + 2);
        asm volatile("cp.async.commit_group;");

        const uint32_t stg = sbase + (uint32_t)(kc % STAGES) * STAGEB;
        const uint32_t bAhi = stg + 0 * MATB;
        const uint32_t bAlo = stg + 1 * MATB;
        const uint32_t bBhi = stg + 2 * MATB;
        const uint32_t bBlo = stg + 3 * MATB;

#pragma unroll
        for (int kh = 0; kh < 2; kh++) {
            const uint32_t ca = ac0 + kh * 2;
            const uint32_t cb = bc0 + kh * 2;
            uint32_t fBh[4][2], fBl[4][2];
#pragma unroll
            for (int ntp = 0; ntp < 2; ntp++) {
                const uint32_t rB = wn * 32 + ntp * 16 + brow4;
                const uint32_t o = swz(rB, cb);
                ldsm_x4(bBhi + o, fBh[ntp * 2]);
                ldsm_x4(bBlo + o, fBl[ntp * 2]);
            }
#pragma unroll
            for (int mt = 0; mt < 4; mt++) {
                const uint32_t rA = wm * 64 + mt * 16 + arow;
                const uint32_t o = swz(rA, ca);
                uint32_t fAh[4], fAl[4];
                ldsm_x4(bAhi + o, fAh);
                ldsm_x4(bAlo + o, fAl);
#pragma unroll
                for (int nt = 0; nt < 4; nt++) {
                    mma_bf16(acc[mt][nt], fAh, fBh[nt]);
                    mma_bf16(acc[mt][nt], fAh, fBl[nt]);
                    mma_bf16(acc[mt][nt], fAl, fBh[nt]);
                }
            }
        }
    }

    float* Cout = (blockIdx.z == 0) ? C : (Cpart + (size_t)(blockIdx.z - 1) * zstride);
    const int gid = lane >> 2;
    const int tig = lane & 3;
#pragma unroll
    for (int mt = 0; mt < 4; mt++) {
        const int r0 = m0 + wm * 64 + mt * 16 + gid;
#pragma unroll
        for (int nt = 0; nt < 4; nt++) {
            const int c = n0 + wn * 32 + nt * 8 + 2 * tig;
            float b0 = 0.0f, b1 = 0.0f;
            if (BIAS) { b0 = bias[c]; b1 = bias[c + 1]; }
            float2 v0 = make_float2(acc[mt][nt][0] + b0, acc[mt][nt][1] + b1);
            float2 v1 = make_float2(acc[mt][nt][2] + b0, acc[mt][nt][3] + b1);
            *(float2*)(&Cout[(size_t)r0 * N + c])       = v0;
            *(float2*)(&Cout[(size_t)(r0 + 8) * N + c]) = v1;
        }
    }
}

// out += part (float4)
__global__ void __launch_bounds__(256)
add_kernel(float* __restrict__ out, const float* __restrict__ part, int n4)
{
    const int i = blockIdx.x * 256 + threadIdx.x;
    if (i < n4) {
        float4 o = ((const float4*)out)[i];
        const float4 p = ((const float4*)part)[i];
        o.x += p.x; o.y += p.y; o.z += p.z; o.w += p.w;
        ((float4*)out)[i] = o;
    }
}

// ---------------------------------------------------------------------------
// Depthwise causal conv (D_CONV=4) + bias + SiLU(z) gate.
// Also emits xh as bf16 hi/lo for the proj GEMM.
// ---------------------------------------------------------------------------
__global__ void __launch_bounds__(256)
conv_gate_kernel(const float* __restrict__ conv_w,
                 const float* __restrict__ conv_b)
{
    const int idx = blockIdx.x * 256 + threadIdx.x;
    const int i = idx & (kDI - 1);
    const int t = (idx >> 11) & (kL - 1);
    const int b = idx >> 21;

    const float* base = g_xz + (size_t)b * kL * (2 * kDI) + i;
    float accv = conv_b[i];
#pragma unroll
    for (int k = 0; k < 4; k++) {
        const int tt = t + k - 3;
        if (tt >= 0) accv += conv_w[i * 4 + k] * base[(size_t)tt * (2 * kDI)];
    }
    const float z = g_xz[((size_t)(b * kL + t)) * (2 * kDI) + kDI + i];
    const float sig = 1.0f / (1.0f + __expf(-z));
    const float xh = accv * (z * sig);
    g_xh[idx] = xh;
    split_bf16(xh, g_xhhi[idx], g_xhlo[idx]);
}

// ---------------------------------------------------------------------------
// proj tile loader: sums the kPKS split-K partials while staging into smem.
// Order z=0..7 matches the old proj_combine exactly (bitwise identical).
// ---------------------------------------------------------------------------
__device__ __forceinline__ void load_proj_tile(float* sp, int b, int c)
{
    for (int idx = threadIdx.x; idx < kTCH * kNP; idx += 256) {
        const int trow = idx / kNP;
        const int n = idx - trow * kNP;
        const int grow = b * kL + c * kTCH + trow;
        float s = 0.0f;
#pragma unroll
        for (int z = 0; z < kPKS; z++)
            s += g_projp[((size_t)z * kRows + grow) * kNPP + n];
        sp[idx] = s;
    }
}

// ---------------------------------------------------------------------------
// Chunked selective scan. delta = exp(softplus(.)) = 1 + exp(.) identity.
// ---------------------------------------------------------------------------
__global__ void __launch_bounds__(256)
scan_pass1_kernel(const float* __restrict__ dt_w,
                  const float* __restrict__ dt_b,
                  const float* __restrict__ A_log)
{
    const int gi = blockIdx.x;
    const int b = gi / (kNCH * (kDI / 256));
    const int c = (gi / (kDI / 256)) % kNCH;
    const int i = (gi % (kDI / 256)) * 256 + threadIdx.x;

    constexpr float kLog2e = 1.4426950408889634f;
    float Arow[kDS], h[kDS], P[kDS];
#pragma unroll
    for (int s = 0; s < kDS; s++) {
        Arow[s] = -__expf(A_log[i * kDS + s]) * kLog2e;
        h[s] = 0.0f;
        P[s] = 1.0f;
    }
    const float dtw = dt_w[i];
    const float dtb = dt_b[i];

    __shared__ float sp[kTCH * kNP];
    load_proj_tile(sp, b, c);
    __syncthreads();

    for (int tt = 0; tt < kTCH; tt++) {
        const int t = c * kTCH + tt;
        const float* row = sp + tt * kNP;
        const float xt = g_xh[((size_t)(b * kL + t)) * kDI + i];
        const float delta = 1.0f + __expf(row[0] * dtw + dtb);
        const float dx = delta * xt;
#pragma unroll
        for (int s = 0; s < kDS; s++) {
            const float a = exp2f(Arow[s] * delta);
            h[s] = a * h[s] + row[1 + s] * dx;
            P[s] *= a;
        }
    }

    const size_t o = (((size_t)(b * kNCH + c)) * kDI + i) * kDS;
#pragma unroll
    for (int v = 0; v < kDS / 4; v++) {
        *(float4*)(g_aprod + o + v * 4) = make_float4(P[v*4], P[v*4+1], P[v*4+2], P[v*4+3]);
        *(float4*)(g_hloc  + o + v * 4) = make_float4(h[v*4], h[v*4+1], h[v*4+2], h[v*4+3]);
    }
}

__global__ void __launch_bounds__(256)
scan_combine_kernel()
{
    const int idx = blockIdx.x * 256 + threadIdx.x;
    const int b = idx >> 15;
    const int rem = idx & ((kDI * kDS) - 1);
    float h = 0.0f;
#pragma unroll 4
    for (int c = 0; c < kNCH; c++) {
        const size_t o = ((size_t)(b * kNCH + c)) * (kDI * kDS) + rem;
        g_hstart[o] = h;
        h = g_aprod[o] * h + g_hloc[o];
    }
}

__global__ void __launch_bounds__(256)
scan_pass3_kernel(const float* __restrict__ dt_w,
                  const float* __restrict__ dt_b,
                  const float* __restrict__ A_log,
                  const float* __restrict__ Dv)
{
    const int gi = blockIdx.x;
    const int b = gi / (kNCH * (kDI / 256));
    const int c = (gi / (kDI / 256)) % kNCH;
    const int i = (gi % (kDI / 256)) * 256 + threadIdx.x;

    constexpr float kLog2e = 1.4426950408889634f;
    float Arow[kDS], h[kDS];
    {
        const size_t o = (((size_t)(b * kNCH + c)) * kDI + i) * kDS;
#pragma unroll
        for (int v = 0; v < kDS / 4; v++) {
            float4 hv = *(const float4*)(g_hstart + o + v * 4);
            h[v*4] = hv.x; h[v*4+1] = hv.y; h[v*4+2] = hv.z; h[v*4+3] = hv.w;
        }
    }
#pragma unroll
    for (int s = 0; s < kDS; s++)
        Arow[s] = -__expf(A_log[i * kDS + s]) * kLog2e;

    const float dtw = dt_w[i];
    const float dtb = dt_b[i];
    const float Di  = Dv[i];

    __shared__ float sp[kTCH * kNP];
    load_proj_tile(sp, b, c);
    __syncthreads();

    for (int tt = 0; tt < kTCH; tt++) {
        const int t = c * kTCH + tt;
        const float* row = sp + tt * kNP;
        const size_t oy = ((size_t)(b * kL + t)) * kDI + i;
        const float xt = g_xh[oy];
        const float delta = 1.0f + __expf(row[0] * dtw + dtb);
        const float dx = delta * xt;
        float yv = 0.0f;
#pragma unroll
        for (int s = 0; s < kDS; s++) {
            const float a = exp2f(Arow[s] * delta);
            h[s] = a * h[s] + row[1 + s] * dx;
            yv += h[s] * row[1 + kDS + s];
        }
        const float yf = yv + Di * xt;
        split_bf16(yf, g_yhi[oy], g_ylo[oy]);
    }
}

// ---------------------------------------------------------------------------
// Launch
// ---------------------------------------------------------------------------
extern "C" void kernel_launch(void* const* d_in, const int* in_sizes, int n_in,
                              void* d_out, int out_size)
{
    const float* x       = (const float*)d_in[0];
    const float* in_w    = (const float*)d_in[1];
    const float* in_b    = (const float*)d_in[2];
    const float* conv_w  = (const float*)d_in[3];
    const float* conv_b  = (const float*)d_in[4];
    const float* xproj_w = (const float*)d_in[5];
    const float* dt_w    = (const float*)d_in[6];
    const float* dt_b    = (const float*)d_in[7];
    const float* A_log   = (const float*)d_in[8];
    const float* Dv      = (const float*)d_in[9];
    const float* out_w   = (const float*)d_in[10];
    float* out = (float*)d_out;

    float *xz_p, *part_p, *projp_p;
    unsigned short *xhi, *xlo, *wihi, *wilo, *wohi, *wolo, *yhi, *ylo;
    unsigned short *xhhi, *xhlo, *wphi, *wplo;
    cudaGetSymbolAddress((void**)&xz_p,    g_xz);
    cudaGetSymbolAddress((void**)&part_p,  g_part);
    cudaGetSymbolAddress((void**)&projp_p, g_projp);
    cudaGetSymbolAddress((void**)&xhi,  g_xhi);
    cudaGetSymbolAddress((void**)&xlo,  g_xlo);
    cudaGetSymbolAddress((void**)&wihi, g_wihi);
    cudaGetSymbolAddress((void**)&wilo, g_wilo);
    cudaGetSymbolAddress((void**)&wohi, g_wohi);
    cudaGetSymbolAddress((void**)&wolo, g_wolo);
    cudaGetSymbolAddress((void**)&wphi, g_wphi);
    cudaGetSymbolAddress((void**)&wplo, g_wplo);
    cudaGetSymbolAddress((void**)&xhhi, g_xhhi);
    cudaGetSymbolAddress((void**)&xhlo, g_xhlo);
    cudaGetSymbolAddress((void**)&yhi,  g_yhi);
    cudaGetSymbolAddress((void**)&ylo,  g_ylo);

    cudaFuncSetAttribute(gemm_bf16x3_kernel<true>,
                         cudaFuncAttributeMaxDynamicSharedMemorySize, TC_SMEM);
    cudaFuncSetAttribute(gemm_bf16x3_kernel<false>,
                         cudaFuncAttributeMaxDynamicSharedMemorySize, TC_SMEM);

    // hi/lo splits (x, in_w, out_w, padded xproj_w) in one launch
    {
        const int n1 = kRows * kDM;
        const int n2 = 2 * kDI * kDM;
        const int n3 = kDM * kDI;
        const int tot = n1 + n2 + n3 + kNPP * kDI;
        cvt4_kernel<<<(tot + 255) / 256, 256>>>(x, xhi, xlo, n1,
                                                in_w, wihi, wilo, n2,
                                                out_w, wohi, wolo, n3,
                                                xproj_w);
    }

    // GEMM1: xz = x @ in_w^T + in_b   (M=2048, N=4096, K=1024)
    {
        dim3 grid((2 * kDI) / 128, kRows / 128, 1);
        gemm_bf16x3_kernel<true><<<grid, 256, TC_SMEM>>>(
            xhi, xlo, wihi, wilo, in_b, xz_p, nullptr, 0, kDM, kDM, 2 * kDI);
    }
    // conv + SiLU gate (also emits xh hi/lo)
    conv_gate_kernel<<<(kRows * kDI) / 256, 256>>>(conv_w, conv_b);
    // xproj via MMA GEMM: proj partials = xh @ wpad^T, split-K=8
    // (combine is fused into the scan passes' tile loader)
    {
        dim3 grid(1, kRows / 128, kPKS);
        gemm_bf16x3_kernel<false><<<grid, 256, TC_SMEM>>>(
            xhhi, xhlo, wphi, wplo, nullptr,
            projp_p, projp_p + (size_t)kRows * kNPP, (size_t)kRows * kNPP,
            kDI, kDI / kPKS, kNPP);
    }
    // chunked selective scan (pass3 emits y as bf16 hi/lo)
    {
        const int grid_scan = kB * kNCH * (kDI / 256);   // 1024
        scan_pass1_kernel<<<grid_scan, 256>>>(dt_w, dt_b, A_log);
        scan_combine_kernel<<<(kB * kDI * kDS) / 256, 256>>>();
        scan_pass3_kernel<<<grid_scan, 256>>>(dt_w, dt_b, A_log, Dv);
    }
    // GEMM2: out = y @ out_w^T  (M=2048, N=1024, K=2048), split-K=2
    {
        dim3 grid(kDM / 128, kRows / 128, 2);
        gemm_bf16x3_kernel<false><<<grid, 256, TC_SMEM>>>(
            yhi, ylo, wohi, wolo, nullptr, out, part_p, 0, kDI, kDI / 2, kDM);
        add_kernel<<<(kRows * kDM / 4 + 255) / 256, 256>>>(out, part_p, kRows * kDM / 4);
    }
}

// round 16
// speedup vs baseline: 1.2750x; 1.2476x over previous
#include <cuda_runtime.h>
#include <cuda_fp16.h>
#include <cstdint>
#include <cstddef>

// ---------------------------------------------------------------------------
// MambaBlock: b=2, L=1024, d_model=1024, d_inner=2048, d_state=16, d_conv=4
// fp16x2 mma.sync GEMMs (D = Ahi*Bhi + Alo*Bhi) + conv/gate + chunked scan
// ---------------------------------------------------------------------------

namespace {
constexpr int kDI   = 2048;
constexpr int kDS   = 16;
constexpr int kL    = 1024;
constexpr int kB    = 2;
constexpr int kDM   = 1024;
constexpr int kRows = kB * kL;        // 2048
constexpr int kNP   = 2 * kDS + 1;    // 33
constexpr int kNPP  = 128;            // padded proj N
constexpr int kNCH  = 64;             // scan chunks
constexpr int kTCH  = kL / kNCH;      // 16
constexpr int kPKS  = 8;              // proj K splits

constexpr int MATB   = 128 * 64;              // 8192 (128 rows x 64B)
constexpr int STAGEB = 3 * MATB;              // 24576 (Ahi|Alo|Bhi)
constexpr int STAGES = 3;
constexpr int TC_SMEM = STAGES * STAGEB;      // 73728 -> 2 CTAs/SM
}

// Scratch (allocation-free rule: device globals)
__device__ float g_xz[(size_t)kRows * 2 * kDI];
__device__ float g_xh[(size_t)kRows * kDI];
__device__ float g_projp[(size_t)kPKS * kRows * kNPP];
__device__ float g_part[(size_t)kRows * kDM];
__device__ float g_aprod [(size_t)kB * kNCH * kDI * kDS];
__device__ float g_hloc  [(size_t)kB * kNCH * kDI * kDS];
__device__ float g_hstart[(size_t)kB * kNCH * kDI * kDS];
__device__ unsigned short g_xhi [(size_t)kRows * kDM];
__device__ unsigned short g_xlo [(size_t)kRows * kDM];
__device__ unsigned short g_wihi[(size_t)2 * kDI * kDM];
__device__ unsigned short g_wohi[(size_t)kDM * kDI];
__device__ unsigned short g_wphi[(size_t)kNPP * kDI];
__device__ unsigned short g_xhhi[(size_t)kRows * kDI];
__device__ unsigned short g_xhlo[(size_t)kRows * kDI];
__device__ unsigned short g_yhi [(size_t)kRows * kDI];
__device__ unsigned short g_ylo [(size_t)kRows * kDI];

// ---------------------------------------------------------------------------
// PTX helpers
// ---------------------------------------------------------------------------
__device__ __forceinline__ uint32_t smem_u32(const void* p) {
    uint32_t a;
    asm("{ .reg .u64 t; cvta.to.shared.u64 t, %1; cvt.u32.u64 %0, t; }" : "=r"(a) : "l"(p));
    return a;
}
__device__ __forceinline__ void cp16(uint32_t saddr, const void* gaddr) {
    asm volatile("cp.async.cg.shared.global [%0], [%1], 16;" :: "r"(saddr), "l"(gaddr));
}
__device__ __forceinline__ void ldsm_x4(uint32_t a, uint32_t r[4]) {
    asm volatile("ldmatrix.sync.aligned.m8n8.x4.shared.b16 {%0,%1,%2,%3}, [%4];"
                 : "=r"(r[0]), "=r"(r[1]), "=r"(r[2]), "=r"(r[3]) : "r"(a));
}
__device__ __forceinline__ void mma_f16(float c[4], const uint32_t a[4], const uint32_t b[2]) {
    asm volatile(
        "mma.sync.aligned.m16n8k16.row.col.f32.f16.f16.f32 "
        "{%0,%1,%2,%3}, {%4,%5,%6,%7}, {%8,%9}, {%0,%1,%2,%3};"
        : "+f"(c[0]), "+f"(c[1]), "+f"(c[2]), "+f"(c[3])
        : "r"(a[0]), "r"(a[1]), "r"(a[2]), "r"(a[3]), "r"(b[0]), "r"(b[1]));
}
__device__ __forceinline__ uint32_t swz(uint32_t r, uint32_t c) {
    return r * 64u + ((c ^ ((r >> 1) & 3u)) << 4);
}
__device__ __forceinline__ void split_fp16(float x, unsigned short& hi, unsigned short& lo) {
    const __half h = __float2half_rn(x);
    hi = __half_as_ushort(h);
    lo = __half_as_ushort(__float2half_rn(x - __half2float(h)));
}
__device__ __forceinline__ unsigned short hi_fp16(float x) {
    return __half_as_ushort(__float2half_rn(x));
}

// ---------------------------------------------------------------------------
// conversions: x (hi/lo), in_w (hi), out_w (hi), padded xproj_w (hi) — 1 launch
// ---------------------------------------------------------------------------
__global__ void __launch_bounds__(256)
cvt4_kernel(const float* __restrict__ x,
            const float* __restrict__ in_w,
            const float* __restrict__ out_w,
            const float* __restrict__ wp)
{
    constexpr int n1 = kRows * kDM;        // x
    constexpr int n2 = 2 * kDI * kDM;      // in_w
    constexpr int n3 = kDM * kDI;          // out_w
    int i = blockIdx.x * 256 + threadIdx.x;
    if (i < n1) { split_fp16(x[i], g_xhi[i], g_xlo[i]); return; }
    i -= n1;
    if (i < n2) { g_wihi[i] = hi_fp16(in_w[i]); return; }
    i -= n2;
    if (i < n3) { g_wohi[i] = hi_fp16(out_w[i]); return; }
    i -= n3;
    if (i >= kNPP * kDI) return;
    const int n = i >> 11;
    g_wphi[i] = hi_fp16((n < kNP) ? wp[i] : 0.0f);
}

// ---------------------------------------------------------------------------
// fp16x2 NT GEMM: C[m,n] = sum_{k in [z*KL,(z+1)*KL)} A[m,k]*B[n,k] (+bias[n])
// D = Ahi*Bhi + Alo*Bhi (Ahi*Blo term dropped; B has no lo matrix at all).
// z=0 writes C; z>=1 writes Cpart + (z-1)*zstride.
// ---------------------------------------------------------------------------
template <bool BIAS>
__global__ void __launch_bounds__(256, 2)
gemm_fp16x2_kernel(const unsigned short* __restrict__ Ahi,
                   const unsigned short* __restrict__ Alo,
                   const unsigned short* __restrict__ Bhi,
                   const float* __restrict__ bias, float* __restrict__ C,
                   float* __restrict__ Cpart, size_t zstride, int K, int KL, int N)
{
    extern __shared__ char sm[];
    const uint32_t sbase = smem_u32(sm);
    const int tid  = threadIdx.x;
    const int wid  = tid >> 5;
    const int lane = tid & 31;
    const int m0 = blockIdx.y * 128;
    const int n0 = blockIdx.x * 128;
    const int koff = blockIdx.z * KL;
    const int wm = wid & 1;
    const int wn = wid >> 1;

    const unsigned short* mats[3] = {
        Ahi + (size_t)m0 * K + koff,
        Alo + (size_t)m0 * K + koff,
        Bhi + (size_t)n0 * K + koff };

    const int NK = KL >> 5;

    // loader: 1536 16B-chunks per stage, 6 per thread; matrix = j>>1 (compile-time)
    auto issue_stage = [&](int kc) {
        const uint32_t sb = sbase + (uint32_t)(kc % STAGES) * STAGEB;
        const size_t kcol = (size_t)kc * 64;
#pragma unroll
        for (int j = 0; j < 6; j++) {
            const int m = j >> 1;                       // 0,0,1,1,2,2
            const int w = (j & 1) * 256 + tid;          // 0..511 within matrix
            const uint32_t row = (uint32_t)(w >> 2);
            const uint32_t c16 = (uint32_t)(w & 3);
            cp16(sb + m * MATB + swz(row, c16),
                 (const char*)mats[m] + (size_t)row * K * 2 + c16 * 16 + kcol);
        }
    };

    issue_stage(0);
    asm volatile("cp.async.commit_group;");
    issue_stage(1);
    asm volatile("cp.async.commit_group;");

    float acc[4][4][4];
#pragma unroll
    for (int mt = 0; mt < 4; mt++)
#pragma unroll
        for (int nt = 0; nt < 4; nt++)
#pragma unroll
            for (int r = 0; r < 4; r++) acc[mt][nt][r] = 0.0f;

    const int ag = lane >> 3;
    const uint32_t arow = (ag & 1) * 8 + (lane & 7);
    const uint32_t ac0  = (uint32_t)(ag >> 1);
    // B x4 addressing (validated R12)
    const uint32_t brow4 = ((lane >> 4) & 1) * 8 + (lane & 7);
    const uint32_t bc0   = (uint32_t)((lane >> 3) & 1);

    for (int kc = 0; kc < NK; kc++) {
        asm volatile("cp.async.wait_group 1;");
        __syncthreads();
        if (kc + 2 < NK) issue_stage(kc + 2);
        asm volatile("cp.async.commit_group;");

        const uint32_t stg = sbase + (uint32_t)(kc % STAGES) * STAGEB;
        const uint32_t bAhi = stg + 0 * MATB;
        const uint32_t bAlo = stg + 1 * MATB;
        const uint32_t bBhi = stg + 2 * MATB;

#pragma unroll
        for (int kh = 0; kh < 2; kh++) {
            const uint32_t ca = ac0 + kh * 2;
            const uint32_t cb = bc0 + kh * 2;
            uint32_t fBh[4][2];
#pragma unroll
            for (int ntp = 0; ntp < 2; ntp++) {
                const uint32_t rB = wn * 32 + ntp * 16 + brow4;
                ldsm_x4(bBhi + swz(rB, cb), fBh[ntp * 2]);
            }
#pragma unroll
            for (int mt = 0; mt < 4; mt++) {
                const uint32_t rA = wm * 64 + mt * 16 + arow;
                const uint32_t o = swz(rA, ca);
                uint32_t fAh[4], fAl[4];
                ldsm_x4(bAhi + o, fAh);
                ldsm_x4(bAlo + o, fAl);
#pragma unroll
                for (int nt = 0; nt < 4; nt++) {
                    mma_f16(acc[mt][nt], fAh, fBh[nt]);
                    mma_f16(acc[mt][nt], fAl, fBh[nt]);
                }
            }
        }
    }

    float* Cout = (blockIdx.z == 0) ? C : (Cpart + (size_t)(blockIdx.z - 1) * zstride);
    const int gid = lane >> 2;
    const int tig = lane & 3;
#pragma unroll
    for (int mt = 0; mt < 4; mt++) {
        const int r0 = m0 + wm * 64 + mt * 16 + gid;
#pragma unroll
        for (int nt = 0; nt < 4; nt++) {
            const int c = n0 + wn * 32 + nt * 8 + 2 * tig;
            float b0 = 0.0f, b1 = 0.0f;
            if (BIAS) { b0 = bias[c]; b1 = bias[c + 1]; }
            float2 v0 = make_float2(acc[mt][nt][0] + b0, acc[mt][nt][1] + b1);
            float2 v1 = make_float2(acc[mt][nt][2] + b0, acc[mt][nt][3] + b1);
            *(float2*)(&Cout[(size_t)r0 * N + c])       = v0;
            *(float2*)(&Cout[(size_t)(r0 + 8) * N + c]) = v1;
        }
    }
}

// out += part (float4)
__global__ void __launch_bounds__(256)
add_kernel(float* __restrict__ out, const float* __restrict__ part, int n4)
{
    const int i = blockIdx.x * 256 + threadIdx.x;
    if (i < n4) {
        float4 o = ((const float4*)out)[i];
        const float4 p = ((const float4*)part)[i];
        o.x += p.x; o.y += p.y; o.z += p.z; o.w += p.w;
        ((float4*)out)[i] = o;
    }
}

// ---------------------------------------------------------------------------
// Depthwise causal conv (D_CONV=4) + bias + SiLU(z) gate.
// Also emits xh as fp16 hi/lo for the proj GEMM.
// ---------------------------------------------------------------------------
__global__ void __launch_bounds__(256)
conv_gate_kernel(const float* __restrict__ conv_w,
                 const float* __restrict__ conv_b)
{
    const int idx = blockIdx.x * 256 + threadIdx.x;
    const int i = idx & (kDI - 1);
    const int t = (idx >> 11) & (kL - 1);
    const int b = idx >> 21;

    const float* base = g_xz + (size_t)b * kL * (2 * kDI) + i;
    float accv = conv_b[i];
#pragma unroll
    for (int k = 0; k < 4; k++) {
        const int tt = t + k - 3;
        if (tt >= 0) accv += conv_w[i * 4 + k] * base[(size_t)tt * (2 * kDI)];
    }
    const float z = g_xz[((size_t)(b * kL + t)) * (2 * kDI) + kDI + i];
    const float sig = 1.0f / (1.0f + __expf(-z));
    const float xh = accv * (z * sig);
    g_xh[idx] = xh;
    split_fp16(xh, g_xhhi[idx], g_xhlo[idx]);
}

// ---------------------------------------------------------------------------
// proj tile loader: sums the kPKS split-K partials while staging into smem.
// ---------------------------------------------------------------------------
__device__ __forceinline__ void load_proj_tile(float* sp, int b, int c)
{
    for (int idx = threadIdx.x; idx < kTCH * kNP; idx += 256) {
        const int trow = idx / kNP;
        const int n = idx - trow * kNP;
        const int grow = b * kL + c * kTCH + trow;
        float s = 0.0f;
#pragma unroll
        for (int z = 0; z < kPKS; z++)
            s += g_projp[((size_t)z * kRows + grow) * kNPP + n];
        sp[idx] = s;
    }
}

// ---------------------------------------------------------------------------
// Chunked selective scan. delta = exp(softplus(.)) = 1 + exp(.) identity.
// ---------------------------------------------------------------------------
__global__ void __launch_bounds__(256)
scan_pass1_kernel(const float* __restrict__ dt_w,
                  const float* __restrict__ dt_b,
                  const float* __restrict__ A_log)
{
    const int gi = blockIdx.x;
    const int b = gi / (kNCH * (kDI / 256));
    const int c = (gi / (kDI / 256)) % kNCH;
    const int i = (gi % (kDI / 256)) * 256 + threadIdx.x;

    constexpr float kLog2e = 1.4426950408889634f;
    float Arow[kDS], h[kDS], P[kDS];
#pragma unroll
    for (int s = 0; s < kDS; s++) {
        Arow[s] = -__expf(A_log[i * kDS + s]) * kLog2e;
        h[s] = 0.0f;
        P[s] = 1.0f;
    }
    const float dtw = dt_w[i];
    const float dtb = dt_b[i];

    __shared__ float sp[kTCH * kNP];
    load_proj_tile(sp, b, c);
    __syncthreads();

    for (int tt = 0; tt < kTCH; tt++) {
        const int t = c * kTCH + tt;
        const float* row = sp + tt * kNP;
        const float xt = g_xh[((size_t)(b * kL + t)) * kDI + i];
        const float delta = 1.0f + __expf(row[0] * dtw + dtb);
        const float dx = delta * xt;
#pragma unroll
        for (int s = 0; s < kDS; s++) {
            const float a = exp2f(Arow[s] * delta);
            h[s] = a * h[s] + row[1 + s] * dx;
            P[s] *= a;
        }
    }

    const size_t o = (((size_t)(b * kNCH + c)) * kDI + i) * kDS;
#pragma unroll
    for (int v = 0; v < kDS / 4; v++) {
        *(float4*)(g_aprod + o + v * 4) = make_float4(P[v*4], P[v*4+1], P[v*4+2], P[v*4+3]);
        *(float4*)(g_hloc  + o + v * 4) = make_float4(h[v*4], h[v*4+1], h[v*4+2], h[v*4+3]);
    }
}

__global__ void __launch_bounds__(256)
scan_combine_kernel()
{
    const int idx = blockIdx.x * 256 + threadIdx.x;
    const int b = idx >> 15;
    const int rem = idx & ((kDI * kDS) - 1);
    float h = 0.0f;
#pragma unroll 4
    for (int c = 0; c < kNCH; c++) {
        const size_t o = ((size_t)(b * kNCH + c)) * (kDI * kDS) + rem;
        g_hstart[o] = h;
        h = g_aprod[o] * h + g_hloc[o];
    }
}

__global__ void __launch_bounds__(256)
scan_pass3_kernel(const float* __restrict__ dt_w,
                  const float* __restrict__ dt_b,
                  const float* __restrict__ A_log,
                  const float* __restrict__ Dv)
{
    const int gi = blockIdx.x;
    const int b = gi / (kNCH * (kDI / 256));
    const int c = (gi / (kDI / 256)) % kNCH;
    const int i = (gi % (kDI / 256)) * 256 + threadIdx.x;

    constexpr float kLog2e = 1.4426950408889634f;
    float Arow[kDS], h[kDS];
    {
        const size_t o = (((size_t)(b * kNCH + c)) * kDI + i) * kDS;
#pragma unroll
        for (int v = 0; v < kDS / 4; v++) {
            float4 hv = *(const float4*)(g_hstart + o + v * 4);
            h[v*4] = hv.x; h[v*4+1] = hv.y; h[v*4+2] = hv.z; h[v*4+3] = hv.w;
        }
    }
#pragma unroll
    for (int s = 0; s < kDS; s++)
        Arow[s] = -__expf(A_log[i * kDS + s]) * kLog2e;

    const float dtw = dt_w[i];
    const float dtb = dt_b[i];
    const float Di  = Dv[i];

    __shared__ float sp[kTCH * kNP];
    load_proj_tile(sp, b, c);
    __syncthreads();

    for (int tt = 0; tt < kTCH; tt++) {
        const int t = c * kTCH + tt;
        const float* row = sp + tt * kNP;
        const size_t oy = ((size_t)(b * kL + t)) * kDI + i;
        const float xt = g_xh[oy];
        const float delta = 1.0f + __expf(row[0] * dtw + dtb);
        const float dx = delta * xt;
        float yv = 0.0f;
#pragma unroll
        for (int s = 0; s < kDS; s++) {
            const float a = exp2f(Arow[s] * delta);
            h[s] = a * h[s] + row[1 + s] * dx;
            yv += h[s] * row[1 + kDS + s];
        }
        const float yf = yv + Di * xt;
        split_fp16(yf, g_yhi[oy], g_ylo[oy]);
    }
}

// ---------------------------------------------------------------------------
// Launch
// ---------------------------------------------------------------------------
extern "C" void kernel_launch(void* const* d_in, const int* in_sizes, int n_in,
                              void* d_out, int out_size)
{
    const float* x       = (const float*)d_in[0];
    const float* in_w    = (const float*)d_in[1];
    const float* in_b    = (const float*)d_in[2];
    const float* conv_w  = (const float*)d_in[3];
    const float* conv_b  = (const float*)d_in[4];
    const float* xproj_w = (const float*)d_in[5];
    const float* dt_w    = (const float*)d_in[6];
    const float* dt_b    = (const float*)d_in[7];
    const float* A_log   = (const float*)d_in[8];
    const float* Dv      = (const float*)d_in[9];
    const float* out_w   = (const float*)d_in[10];
    float* out = (float*)d_out;

    float *xz_p, *part_p, *projp_p;
    unsigned short *xhi, *xlo, *wihi, *wohi, *wphi, *xhhi, *xhlo, *yhi, *ylo;
    cudaGetSymbolAddress((void**)&xz_p,    g_xz);
    cudaGetSymbolAddress((void**)&part_p,  g_part);
    cudaGetSymbolAddress((void**)&projp_p, g_projp);
    cudaGetSymbolAddress((void**)&xhi,  g_xhi);
    cudaGetSymbolAddress((void**)&xlo,  g_xlo);
    cudaGetSymbolAddress((void**)&wihi, g_wihi);
    cudaGetSymbolAddress((void**)&wohi, g_wohi);
    cudaGetSymbolAddress((void**)&wphi, g_wphi);
    cudaGetSymbolAddress((void**)&xhhi, g_xhhi);
    cudaGetSymbolAddress((void**)&xhlo, g_xhlo);
    cudaGetSymbolAddress((void**)&yhi,  g_yhi);
    cudaGetSymbolAddress((void**)&ylo,  g_ylo);

    cudaFuncSetAttribute(gemm_fp16x2_kernel<true>,
                         cudaFuncAttributeMaxDynamicSharedMemorySize, TC_SMEM);
    cudaFuncSetAttribute(gemm_fp16x2_kernel<false>,
                         cudaFuncAttributeMaxDynamicSharedMemorySize, TC_SMEM);

    // conversions in one launch
    {
        const int tot = kRows * kDM + 2 * kDI * kDM + kDM * kDI + kNPP * kDI;
        cvt4_kernel<<<(tot + 255) / 256, 256>>>(x, in_w, out_w, xproj_w);
    }

    // GEMM1: xz = x @ in_w^T + in_b   (M=2048, N=4096, K=1024)
    {
        dim3 grid((2 * kDI) / 128, kRows / 128, 1);
        gemm_fp16x2_kernel<true><<<grid, 256, TC_SMEM>>>(
            xhi, xlo, wihi, in_b, xz_p, nullptr, 0, kDM, kDM, 2 * kDI);
    }
    // conv + SiLU gate (also emits xh hi/lo)
    conv_gate_kernel<<<(kRows * kDI) / 256, 256>>>(conv_w, conv_b);
    // xproj via MMA GEMM: proj partials = xh @ wpad^T, split-K=8
    // (combine fused into the scan passes' tile loader)
    {
        dim3 grid(1, kRows / 128, kPKS);
        gemm_fp16x2_kernel<false><<<grid, 256, TC_SMEM>>>(
            xhhi, xhlo, wphi, nullptr,
            projp_p, projp_p + (size_t)kRows * kNPP, (size_t)kRows * kNPP,
            kDI, kDI / kPKS, kNPP);
    }
    // chunked selective scan (pass3 emits y as fp16 hi/lo)
    {
        const int grid_scan = kB * kNCH * (kDI / 256);   // 1024
        scan_pass1_kernel<<<grid_scan, 256>>>(dt_w, dt_b, A_log);
        scan_combine_kernel<<<(kB * kDI * kDS) / 256, 256>>>();
        scan_pass3_kernel<<<grid_scan, 256>>>(dt_w, dt_b, A_log, Dv);
    }
    // GEMM2: out = y @ out_w^T  (M=2048, N=1024, K=2048), split-K=2
    {
        dim3 grid(kDM / 128, kRows / 128, 2);
        gemm_fp16x2_kernel<false><<<grid, 256, TC_SMEM>>>(
            yhi, ylo, wohi, nullptr, out, part_p, 0, kDI, kDI / 2, kDM);
        add_kernel<<<(kRows * kDM / 4 + 255) / 256, 256>>>(out, part_p, kRows * kDM / 4);
    }
}

// round 17
// speedup vs baseline: 1.3093x; 1.0269x over previous
#include <cuda_runtime.h>
#include <cuda_fp16.h>
#include <cstdint>
#include <cstddef>

// ---------------------------------------------------------------------------
// MambaBlock: b=2, L=1024, d_model=1024, d_inner=2048, d_state=16, d_conv=4
// fp16x2 mma.sync GEMMs (D = Ahi*Bhi + Alo*Bhi) + conv/gate + chunked scan
// ---------------------------------------------------------------------------

namespace {
constexpr int kDI   = 2048;
constexpr int kDS   = 16;
constexpr int kL    = 1024;
constexpr int kB    = 2;
constexpr int kDM   = 1024;
constexpr int kRows = kB * kL;        // 2048
constexpr int kNP   = 2 * kDS + 1;    // 33
constexpr int kNPP  = 128;            // padded proj N
constexpr int kNCH  = 64;             // scan chunks
constexpr int kTCH  = kL / kNCH;      // 16
constexpr int kPKS  = 8;              // proj K splits

constexpr int MATB   = 128 * 64;              // 8192 (128 rows x 64B)
constexpr int STAGEB = 3 * MATB;              // 24576 (Ahi|Alo|Bhi)
constexpr int STAGES = 3;
constexpr int TC_SMEM = STAGES * STAGEB;      // 73728 -> 2 CTAs/SM
}

// Scratch (allocation-free rule: device globals)
__device__ float g_xz[(size_t)kRows * 2 * kDI];
__device__ float g_projp[(size_t)kPKS * kRows * kNPP];
__device__ float g_part[(size_t)kRows * kDM];
__device__ float g_aprod [(size_t)kB * kNCH * kDI * kDS];
__device__ float g_hloc  [(size_t)kB * kNCH * kDI * kDS];
__device__ float g_hstart[(size_t)kB * kNCH * kDI * kDS];
__device__ unsigned short g_xhi [(size_t)kRows * kDM];
__device__ unsigned short g_xlo [(size_t)kRows * kDM];
__device__ unsigned short g_wihi[(size_t)2 * kDI * kDM];
__device__ unsigned short g_wohi[(size_t)kDM * kDI];
__device__ unsigned short g_wphi[(size_t)kNPP * kDI];
__device__ unsigned short g_xhhi[(size_t)kRows * kDI];
__device__ unsigned short g_xhlo[(size_t)kRows * kDI];
__device__ unsigned short g_yhi [(size_t)kRows * kDI];
__device__ unsigned short g_ylo [(size_t)kRows * kDI];

// ---------------------------------------------------------------------------
// PTX helpers
// ---------------------------------------------------------------------------
__device__ __forceinline__ uint32_t smem_u32(const void* p) {
    uint32_t a;
    asm("{ .reg .u64 t; cvta.to.shared.u64 t, %1; cvt.u32.u64 %0, t; }" : "=r"(a) : "l"(p));
    return a;
}
__device__ __forceinline__ void cp16(uint32_t saddr, const void* gaddr) {
    asm volatile("cp.async.cg.shared.global [%0], [%1], 16;" :: "r"(saddr), "l"(gaddr));
}
__device__ __forceinline__ void ldsm_x4(uint32_t a, uint32_t r[4]) {
    asm volatile("ldmatrix.sync.aligned.m8n8.x4.shared.b16 {%0,%1,%2,%3}, [%4];"
                 : "=r"(r[0]), "=r"(r[1]), "=r"(r[2]), "=r"(r[3]) : "r"(a));
}
__device__ __forceinline__ void mma_f16(float c[4], const uint32_t a[4], const uint32_t b[2]) {
    asm volatile(
        "mma.sync.aligned.m16n8k16.row.col.f32.f16.f16.f32 "
        "{%0,%1,%2,%3}, {%4,%5,%6,%7}, {%8,%9}, {%0,%1,%2,%3};"
        : "+f"(c[0]), "+f"(c[1]), "+f"(c[2]), "+f"(c[3])
        : "r"(a[0]), "r"(a[1]), "r"(a[2]), "r"(a[3]), "r"(b[0]), "r"(b[1]));
}
__device__ __forceinline__ uint32_t swz(uint32_t r, uint32_t c) {
    return r * 64u + ((c ^ ((r >> 1) & 3u)) << 4);
}
__device__ __forceinline__ void split_fp16(float x, unsigned short& hi, unsigned short& lo) {
    const __half h = __float2half_rn(x);
    hi = __half_as_ushort(h);
    lo = __half_as_ushort(__float2half_rn(x - __half2float(h)));
}
__device__ __forceinline__ unsigned short hi_fp16(float x) {
    return __half_as_ushort(__float2half_rn(x));
}
__device__ __forceinline__ float join_fp16(unsigned short hi, unsigned short lo) {
    return __half2float(__ushort_as_half(hi)) + __half2float(__ushort_as_half(lo));
}

// ---------------------------------------------------------------------------
// conversions (x4-vectorized): x (hi/lo), in_w (hi), out_w (hi), wpad (hi)
// ---------------------------------------------------------------------------
__global__ void __launch_bounds__(256)
cvt4_kernel(const float* __restrict__ x,
            const float* __restrict__ in_w,
            const float* __restrict__ out_w,
            const float* __restrict__ wp)
{
    constexpr int q1 = kRows * kDM / 4;        // x quads
    constexpr int q2 = 2 * kDI * kDM / 4;      // in_w quads
    constexpr int q3 = kDM * kDI / 4;          // out_w quads
    constexpr int q4 = kNPP * kDI / 4;         // wpad quads
    int i = blockIdx.x * 256 + threadIdx.x;
    if (i < q1) {
        const float4 v = ((const float4*)x)[i];
        ushort4 h, l;
        split_fp16(v.x, h.x, l.x); split_fp16(v.y, h.y, l.y);
        split_fp16(v.z, h.z, l.z); split_fp16(v.w, h.w, l.w);
        ((ushort4*)g_xhi)[i] = h;
        ((ushort4*)g_xlo)[i] = l;
        return;
    }
    i -= q1;
    if (i < q2) {
        const float4 v = ((const float4*)in_w)[i];
        ((ushort4*)g_wihi)[i] = make_ushort4(hi_fp16(v.x), hi_fp16(v.y),
                                             hi_fp16(v.z), hi_fp16(v.w));
        return;
    }
    i -= q2;
    if (i < q3) {
        const float4 v = ((const float4*)out_w)[i];
        ((ushort4*)g_wohi)[i] = make_ushort4(hi_fp16(v.x), hi_fp16(v.y),
                                             hi_fp16(v.z), hi_fp16(v.w));
        return;
    }
    i -= q3;
    if (i >= q4) return;
    const int n = (i * 4) >> 11;       // row in padded 128 x 2048 (quad within one row)
    if (n < kNP) {
        const float4 v = ((const float4*)wp)[i];
        ((ushort4*)g_wphi)[i] = make_ushort4(hi_fp16(v.x), hi_fp16(v.y),
                                             hi_fp16(v.z), hi_fp16(v.w));
    } else {
        ((ushort4*)g_wphi)[i] = make_ushort4(0, 0, 0, 0);
    }
}

// ---------------------------------------------------------------------------
// fp16x2 NT GEMM: C[m,n] = sum_{k in [z*KL,(z+1)*KL)} A[m,k]*B[n,k] (+bias[n])
// D = Ahi*Bhi + Alo*Bhi. z=0 writes C; z>=1 writes Cpart + (z-1)*zstride.
// ---------------------------------------------------------------------------
template <bool BIAS>
__global__ void __launch_bounds__(256, 2)
gemm_fp16x2_kernel(const unsigned short* __restrict__ Ahi,
                   const unsigned short* __restrict__ Alo,
                   const unsigned short* __restrict__ Bhi,
                   const float* __restrict__ bias, float* __restrict__ C,
                   float* __restrict__ Cpart, size_t zstride, int K, int KL, int N)
{
    extern __shared__ char sm[];
    const uint32_t sbase = smem_u32(sm);
    const int tid  = threadIdx.x;
    const int wid  = tid >> 5;
    const int lane = tid & 31;
    const int m0 = blockIdx.y * 128;
    const int n0 = blockIdx.x * 128;
    const int koff = blockIdx.z * KL;
    const int wm = wid & 1;
    const int wn = wid >> 1;

    const unsigned short* mats[3] = {
        Ahi + (size_t)m0 * K + koff,
        Alo + (size_t)m0 * K + koff,
        Bhi + (size_t)n0 * K + koff };

    const int NK = KL >> 5;

    auto issue_stage = [&](int kc) {
        const uint32_t sb = sbase + (uint32_t)(kc % STAGES) * STAGEB;
        const size_t kcol = (size_t)kc * 64;
#pragma unroll
        for (int j = 0; j < 6; j++) {
            const int m = j >> 1;                       // 0,0,1,1,2,2
            const int w = (j & 1) * 256 + tid;          // 0..511 within matrix
            const uint32_t row = (uint32_t)(w >> 2);
            const uint32_t c16 = (uint32_t)(w & 3);
            cp16(sb + m * MATB + swz(row, c16),
                 (const char*)mats[m] + (size_t)row * K * 2 + c16 * 16 + kcol);
        }
    };

    issue_stage(0);
    asm volatile("cp.async.commit_group;");
    issue_stage(1);
    asm volatile("cp.async.commit_group;");

    float acc[4][4][4];
#pragma unroll
    for (int mt = 0; mt < 4; mt++)
#pragma unroll
        for (int nt = 0; nt < 4; nt++)
#pragma unroll
            for (int r = 0; r < 4; r++) acc[mt][nt][r] = 0.0f;

    const int ag = lane >> 3;
    const uint32_t arow = (ag & 1) * 8 + (lane & 7);
    const uint32_t ac0  = (uint32_t)(ag >> 1);
    const uint32_t brow4 = ((lane >> 4) & 1) * 8 + (lane & 7);
    const uint32_t bc0   = (uint32_t)((lane >> 3) & 1);

    for (int kc = 0; kc < NK; kc++) {
        asm volatile("cp.async.wait_group 1;");
        __syncthreads();
        if (kc + 2 < NK) issue_stage(kc + 2);
        asm volatile("cp.async.commit_group;");

        const uint32_t stg = sbase + (uint32_t)(kc % STAGES) * STAGEB;
        const uint32_t bAhi = stg + 0 * MATB;
        const uint32_t bAlo = stg + 1 * MATB;
        const uint32_t bBhi = stg + 2 * MATB;

#pragma unroll
        for (int kh = 0; kh < 2; kh++) {
            const uint32_t ca = ac0 + kh * 2;
            const uint32_t cb = bc0 + kh * 2;
            uint32_t fBh[4][2];
#pragma unroll
            for (int ntp = 0; ntp < 2; ntp++) {
                const uint32_t rB = wn * 32 + ntp * 16 + brow4;
                ldsm_x4(bBhi + swz(rB, cb), fBh[ntp * 2]);
            }
#pragma unroll
            for (int mt = 0; mt < 4; mt++) {
                const uint32_t rA = wm * 64 + mt * 16 + arow;
                const uint32_t o = swz(rA, ca);
                uint32_t fAh[4], fAl[4];
                ldsm_x4(bAhi + o, fAh);
                ldsm_x4(bAlo + o, fAl);
#pragma unroll
                for (int nt = 0; nt < 4; nt++) {
                    mma_f16(acc[mt][nt], fAh, fBh[nt]);
                    mma_f16(acc[mt][nt], fAl, fBh[nt]);
                }
            }
        }
    }

    float* Cout = (blockIdx.z == 0) ? C : (Cpart + (size_t)(blockIdx.z - 1) * zstride);
    const int gid = lane >> 2;
    const int tig = lane & 3;
#pragma unroll
    for (int mt = 0; mt < 4; mt++) {
        const int r0 = m0 + wm * 64 + mt * 16 + gid;
#pragma unroll
        for (int nt = 0; nt < 4; nt++) {
            const int c = n0 + wn * 32 + nt * 8 + 2 * tig;
            float b0 = 0.0f, b1 = 0.0f;
            if (BIAS) { b0 = bias[c]; b1 = bias[c + 1]; }
            float2 v0 = make_float2(acc[mt][nt][0] + b0, acc[mt][nt][1] + b1);
            float2 v1 = make_float2(acc[mt][nt][2] + b0, acc[mt][nt][3] + b1);
            *(float2*)(&Cout[(size_t)r0 * N + c])       = v0;
            *(float2*)(&Cout[(size_t)(r0 + 8) * N + c]) = v1;
        }
    }
}

// out += part (float4)
__global__ void __launch_bounds__(256)
add_kernel(float* __restrict__ out, const float* __restrict__ part, int n4)
{
    const int i = blockIdx.x * 256 + threadIdx.x;
    if (i < n4) {
        float4 o = ((const float4*)out)[i];
        const float4 p = ((const float4*)part)[i];
        o.x += p.x; o.y += p.y; o.z += p.z; o.w += p.w;
        ((float4*)out)[i] = o;
    }
}

// ---------------------------------------------------------------------------
// Depthwise causal conv (D_CONV=4) + bias + SiLU(z) gate.
// 2 channels per thread; emits xh ONLY as fp16 hi/lo (scan reconstructs).
// ---------------------------------------------------------------------------
__global__ void __launch_bounds__(256)
conv_gate_kernel(const float* __restrict__ conv_w,
                 const float* __restrict__ conv_b)
{
    const int idx2 = blockIdx.x * 256 + threadIdx.x;   // over kB*kL*kDI/2
    const int i = (idx2 & (kDI / 2 - 1)) * 2;
    const int t = (idx2 >> 10) & (kL - 1);
    const int b = idx2 >> 20;

    const float* base = g_xz + (size_t)b * kL * (2 * kDI) + i;
    float a0 = conv_b[i], a1 = conv_b[i + 1];
#pragma unroll
    for (int k = 0; k < 4; k++) {
        const int tt = t + k - 3;
        if (tt >= 0) {
            const float2 v = *(const float2*)(base + (size_t)tt * (2 * kDI));
            a0 += conv_w[i * 4 + k] * v.x;
            a1 += conv_w[(i + 1) * 4 + k] * v.y;
        }
    }
    const float2 z = *(const float2*)(g_xz + ((size_t)(b * kL + t)) * (2 * kDI) + kDI + i);
    const float s0 = 1.0f / (1.0f + __expf(-z.x));
    const float s1 = 1.0f / (1.0f + __expf(-z.y));
    const float xh0 = a0 * (z.x * s0);
    const float xh1 = a1 * (z.y * s1);

    ushort2 h, l;
    split_fp16(xh0, h.x, l.x);
    split_fp16(xh1, h.y, l.y);
    const size_t oy = ((size_t)(b * kL + t)) * kDI + i;
    *(ushort2*)(g_xhhi + oy) = h;
    *(ushort2*)(g_xhlo + oy) = l;
}

// ---------------------------------------------------------------------------
// proj tile loader: sums the kPKS split-K partials while staging into smem.
// ---------------------------------------------------------------------------
__device__ __forceinline__ void load_proj_tile(float* sp, int b, int c)
{
    for (int idx = threadIdx.x; idx < kTCH * kNP; idx += 256) {
        const int trow = idx / kNP;
        const int n = idx - trow * kNP;
        const int grow = b * kL + c * kTCH + trow;
        float s = 0.0f;
#pragma unroll
        for (int z = 0; z < kPKS; z++)
            s += g_projp[((size_t)z * kRows + grow) * kNPP + n];
        sp[idx] = s;
    }
}

// ---------------------------------------------------------------------------
// Chunked selective scan. delta = exp(softplus(.)) = 1 + exp(.) identity.
// ---------------------------------------------------------------------------
__global__ void __launch_bounds__(256)
scan_pass1_kernel(const float* __restrict__ dt_w,
                  const float* __restrict__ dt_b,
                  const float* __restrict__ A_log)
{
    const int gi = blockIdx.x;
    const int b = gi / (kNCH * (kDI / 256));
    const int c = (gi / (kDI / 256)) % kNCH;
    const int i = (gi % (kDI / 256)) * 256 + threadIdx.x;

    constexpr float kLog2e = 1.4426950408889634f;
    float Arow[kDS], h[kDS], P[kDS];
#pragma unroll
    for (int s = 0; s < kDS; s++) {
        Arow[s] = -__expf(A_log[i * kDS + s]) * kLog2e;
        h[s] = 0.0f;
        P[s] = 1.0f;
    }
    const float dtw = dt_w[i];
    const float dtb = dt_b[i];

    __shared__ float sp[kTCH * kNP];
    load_proj_tile(sp, b, c);
    __syncthreads();

    for (int tt = 0; tt < kTCH; tt++) {
        const int t = c * kTCH + tt;
        const float* row = sp + tt * kNP;
        const size_t oy = ((size_t)(b * kL + t)) * kDI + i;
        const float xt = join_fp16(g_xhhi[oy], g_xhlo[oy]);
        const float delta = 1.0f + __expf(row[0] * dtw + dtb);
        const float dx = delta * xt;
#pragma unroll
        for (int s = 0; s < kDS; s++) {
            const float a = exp2f(Arow[s] * delta);
            h[s] = a * h[s] + row[1 + s] * dx;
            P[s] *= a;
        }
    }

    const size_t o = (((size_t)(b * kNCH + c)) * kDI + i) * kDS;
#pragma unroll
    for (int v = 0; v < kDS / 4; v++) {
        *(float4*)(g_aprod + o + v * 4) = make_float4(P[v*4], P[v*4+1], P[v*4+2], P[v*4+3]);
        *(float4*)(g_hloc  + o + v * 4) = make_float4(h[v*4], h[v*4+1], h[v*4+2], h[v*4+3]);
    }
}

__global__ void __launch_bounds__(256)
scan_combine_kernel()
{
    const int idx = blockIdx.x * 256 + threadIdx.x;
    const int b = idx >> 15;
    const int rem = idx & ((kDI * kDS) - 1);
    float h = 0.0f;
#pragma unroll 4
    for (int c = 0; c < kNCH; c++) {
        const size_t o = ((size_t)(b * kNCH + c)) * (kDI * kDS) + rem;
        g_hstart[o] = h;
        h = g_aprod[o] * h + g_hloc[o];
    }
}

__global__ void __launch_bounds__(256)
scan_pass3_kernel(const float* __restrict__ dt_w,
                  const float* __restrict__ dt_b,
                  const float* __restrict__ A_log,
                  const float* __restrict__ Dv)
{
    const int gi = blockIdx.x;
    const int b = gi / (kNCH * (kDI / 256));
    const int c = (gi / (kDI / 256)) % kNCH;
    const int i = (gi % (kDI / 256)) * 256 + threadIdx.x;

    constexpr float kLog2e = 1.4426950408889634f;
    float Arow[kDS], h[kDS];
    {
        const size_t o = (((size_t)(b * kNCH + c)) * kDI + i) * kDS;
#pragma unroll
        for (int v = 0; v < kDS / 4; v++) {
            float4 hv = *(const float4*)(g_hstart + o + v * 4);
            h[v*4] = hv.x; h[v*4+1] = hv.y; h[v*4+2] = hv.z; h[v*4+3] = hv.w;
        }
    }
#pragma unroll
    for (int s = 0; s < kDS; s++)
        Arow[s] = -__expf(A_log[i * kDS + s]) * kLog2e;

    const float dtw = dt_w[i];
    const float dtb = dt_b[i];
    const float Di  = Dv[i];

    __shared__ float sp[kTCH * kNP];
    load_proj_tile(sp, b, c);
    __syncthreads();

    for (int tt = 0; tt < kTCH; tt++) {
        const int t = c * kTCH + tt;
        const float* row = sp + tt * kNP;
        const size_t oy = ((size_t)(b * kL + t)) * kDI + i;
        const float xt = join_fp16(g_xhhi[oy], g_xhlo[oy]);
        const float delta = 1.0f + __expf(row[0] * dtw + dtb);
        const float dx = delta * xt;
        float yv = 0.0f;
#pragma unroll
        for (int s = 0; s < kDS; s++) {
            const float a = exp2f(Arow[s] * delta);
            h[s] = a * h[s] + row[1 + s] * dx;
            yv += h[s] * row[1 + kDS + s];
        }
        const float yf = yv + Di * xt;
        split_fp16(yf, g_yhi[oy], g_ylo[oy]);
    }
}

// ---------------------------------------------------------------------------
// Launch
// ---------------------------------------------------------------------------
extern "C" void kernel_launch(void* const* d_in, const int* in_sizes, int n_in,
                              void* d_out, int out_size)
{
    const float* x       = (const float*)d_in[0];
    const float* in_w    = (const float*)d_in[1];
    const float* in_b    = (const float*)d_in[2];
    const float* conv_w  = (const float*)d_in[3];
    const float* conv_b  = (const float*)d_in[4];
    const float* xproj_w = (const float*)d_in[5];
    const float* dt_w    = (const float*)d_in[6];
    const float* dt_b    = (const float*)d_in[7];
    const float* A_log   = (const float*)d_in[8];
    const float* Dv      = (const float*)d_in[9];
    const float* out_w   = (const float*)d_in[10];
    float* out = (float*)d_out;

    float *xz_p, *part_p, *projp_p;
    unsigned short *xhi, *xlo, *wihi, *wohi, *wphi, *xhhi, *xhlo, *yhi, *ylo;
    cudaGetSymbolAddress((void**)&xz_p,    g_xz);
    cudaGetSymbolAddress((void**)&part_p,  g_part);
    cudaGetSymbolAddress((void**)&projp_p, g_projp);
    cudaGetSymbolAddress((void**)&xhi,  g_xhi);
    cudaGetSymbolAddress((void**)&xlo,  g_xlo);
    cudaGetSymbolAddress((void**)&wihi, g_wihi);
    cudaGetSymbolAddress((void**)&wohi, g_wohi);
    cudaGetSymbolAddress((void**)&wphi, g_wphi);
    cudaGetSymbolAddress((void**)&xhhi, g_xhhi);
    cudaGetSymbolAddress((void**)&xhlo, g_xhlo);
    cudaGetSymbolAddress((void**)&yhi,  g_yhi);
    cudaGetSymbolAddress((void**)&ylo,  g_ylo);

    cudaFuncSetAttribute(gemm_fp16x2_kernel<true>,
                         cudaFuncAttributeMaxDynamicSharedMemorySize, TC_SMEM);
    cudaFuncSetAttribute(gemm_fp16x2_kernel<false>,
                         cudaFuncAttributeMaxDynamicSharedMemorySize, TC_SMEM);

    // conversions in one vectorized launch
    {
        const int totq = (kRows * kDM + 2 * kDI * kDM + kDM * kDI + kNPP * kDI) / 4;
        cvt4_kernel<<<(totq + 255) / 256, 256>>>(x, in_w, out_w, xproj_w);
    }

    // GEMM1: xz = x @ in_w^T + in_b   (M=2048, N=4096, K=1024)
    {
        dim3 grid((2 * kDI) / 128, kRows / 128, 1);
        gemm_fp16x2_kernel<true><<<grid, 256, TC_SMEM>>>(
            xhi, xlo, wihi, in_b, xz_p, nullptr, 0, kDM, kDM, 2 * kDI);
    }
    // conv + SiLU gate (emits xh as fp16 hi/lo only)
    conv_gate_kernel<<<(kRows * kDI / 2) / 256, 256>>>(conv_w, conv_b);
    // xproj via MMA GEMM: proj partials = xh @ wpad^T, split-K=8
    // (combine fused into the scan passes' tile loader)
    {
        dim3 grid(1, kRows / 128, kPKS);
        gemm_fp16x2_kernel<false><<<grid, 256, TC_SMEM>>>(
            xhhi, xhlo, wphi, nullptr,
            projp_p, projp_p + (size_t)kRows * kNPP, (size_t)kRows * kNPP,
            kDI, kDI / kPKS, kNPP);
    }
    // chunked selective scan (pass3 emits y as fp16 hi/lo)
    {
        const int grid_scan = kB * kNCH * (kDI / 256);   // 1024
        scan_pass1_kernel<<<grid_scan, 256>>>(dt_w, dt_b, A_log);
        scan_combine_kernel<<<(kB * kDI * kDS) / 256, 256>>>();
        scan_pass3_kernel<<<grid_scan, 256>>>(dt_w, dt_b, A_log, Dv);
    }
    // GEMM2: out = y @ out_w^T  (M=2048, N=1024, K=2048), split-K=2
    {
        dim3 grid(kDM / 128, kRows / 128, 2);
        gemm_fp16x2_kernel<false><<<grid, 256, TC_SMEM>>>(
            yhi, ylo, wohi, nullptr, out, part_p, 0, kDI, kDI / 2, kDM);
        add_kernel<<<(kRows * kDM / 4 + 255) / 256, 256>>>(out, part_p, kRows * kDM / 4);
    }
}